// round 8
// baseline (speedup 1.0000x reference)
#include <cuda_runtime.h>
#include <math.h>

#define Bsz 1024
#define Ssz 350
#define Vsz 41
#define NCTA 128
#define NTHR 256

typedef unsigned long long u64;

// ---------------- persistent device scratch ----------------
__device__ float g_G0[41 * 768];          // [v][gatecol] = bih0 + Wih0 @ emb[v]
__device__ float g_h0r[2 * 256 * 1024];   // ring: [buf][k][row]
__device__ float g_h1r[2 * 128 * 1024];
__device__ float g_h2r[2 * 32 * 1024];
__device__ int   g_tokT[Ssz * 1024];      // [step][row]
__device__ int   g_flags[Ssz * 16 * 3];   // [step][pod][phase]

// ---------------- helpers ----------------
__device__ __forceinline__ u64 fma2(u64 a, u64 b, u64 c) {
    u64 d; asm("fma.rn.f32x2 %0,%1,%2,%3;" : "=l"(d) : "l"(a), "l"(b), "l"(c)); return d;
}
__device__ __forceinline__ u64 pk2(float x, float y) {
    u64 d; asm("mov.b64 %0,{%1,%2};" : "=l"(d) : "f"(x), "f"(y)); return d;
}
__device__ __forceinline__ void up2(u64 a, float& x, float& y) {
    asm("mov.b64 {%0,%1}, %2;" : "=f"(x), "=f"(y) : "l"(a));
}
__device__ __forceinline__ ulonglong2 ldcg2(const u64* p) {
    ulonglong2 v;
    asm volatile("ld.global.cg.v2.u64 {%0,%1},[%2];" : "=l"(v.x), "=l"(v.y) : "l"(p));
    return v;
}
__device__ __forceinline__ u64 ldcg1(const u64* p) {
    u64 v; asm volatile("ld.global.cg.u64 %0,[%1];" : "=l"(v) : "l"(p)); return v;
}
__device__ __forceinline__ float ldcgf(const float* p) {
    float v; asm volatile("ld.global.cg.f32 %0,[%1];" : "=f"(v) : "l"(p)); return v;
}
__device__ __forceinline__ float sigf(float x) {
    return __fdividef(1.0f, 1.0f + __expf(-x));
}
__device__ __forceinline__ float tanh_(float x) {
    float ax = fabsf(x);
    float e = __expf(-2.0f * ax);
    float t = __fdividef(1.0f - e, 1.0f + e);
    return copysignf(t, x);
}

__device__ __forceinline__ void pod_barrier(int* flag) {
    __threadfence();
    __syncthreads();
    if (threadIdx.x == 0) {
        atomicAdd(flag, 1);
        while (*(volatile int*)flag < 8) __nanosleep(64);
        __threadfence();
    }
    __syncthreads();
}

// ---------------- flag reset (runs before k_main each replay) ----------------
__global__ void k_zero() {
    int i = blockIdx.x * blockDim.x + threadIdx.x;
    if (i < Ssz * 16 * 3) g_flags[i] = 0;
}

// ---------------- prep: Hinit -> ring slot 1, G0, token transpose ----------------
__global__ void k_prep(const float* __restrict__ latent, const float* __restrict__ W_emb,
                       const float* __restrict__ b_emb, const float* __restrict__ W_init,
                       const float* __restrict__ b_init, const float* __restrict__ Wih0,
                       const float* __restrict__ bih0, const int* __restrict__ tokens) {
    const int b = blockIdx.x, tid = threadIdx.x;
    if (b < 128) {
        __shared__ float lat[8 * 512];
        const int b0 = b * 8;
        for (int i = tid; i < 8 * 512; i += 256) lat[i] = latent[(size_t)b0 * 512 + i];
        __syncthreads();
        for (int c = tid; c < 416; c += 256) {
            float acc[8];
            float bi = b_init[c];
#pragma unroll
            for (int r = 0; r < 8; r++) acc[r] = bi;
            const float* w = W_init + (size_t)c * 512;
            for (int k = 0; k < 512; k += 4) {
                float4 wv = *(const float4*)(w + k);
#pragma unroll
                for (int r = 0; r < 8; r++) {
                    acc[r] += wv.x * lat[r * 512 + k];
                    acc[r] += wv.y * lat[r * 512 + k + 1];
                    acc[r] += wv.z * lat[r * 512 + k + 2];
                    acc[r] += wv.w * lat[r * 512 + k + 3];
                }
            }
#pragma unroll
            for (int r = 0; r < 8; r++) {
                int row = b0 + r;
                if (c < 256)      g_h0r[262144 + c * 1024 + row] = acc[r];
                else if (c < 384) g_h1r[131072 + (c - 256) * 1024 + row] = acc[r];
                else              g_h2r[32768 + (c - 384) * 1024 + row] = acc[r];
            }
        }
    } else if (b < 169) {
        const int v = b - 128;
        __shared__ float emb[512];
        for (int k = tid; k < 512; k += 256) emb[k] = W_emb[k * Vsz + v] + b_emb[k];
        __syncthreads();
        for (int j = tid; j < 768; j += 256) {
            float acc = bih0[j];
            const float* w = Wih0 + (size_t)j * 512;
            for (int k = 0; k < 512; k += 4) {
                float4 wv = *(const float4*)(w + k);
                acc += wv.x * emb[k] + wv.y * emb[k + 1] + wv.z * emb[k + 2] + wv.w * emb[k + 3];
            }
            g_G0[v * 768 + j] = acc;
        }
    } else {
        for (int i = (b - 169) * 256 + tid; i < Ssz * 1024; i += 8 * 256) {
            int stt = i >> 10, row = i & 1023;
            g_tokT[i] = (stt == 0) ? 1 : tokens[(size_t)row * Ssz + stt];
        }
    }
}

// smem float offsets
#define O_WA   0
#define O_WB1  24576
#define O_WB2  36864
#define O_WC1  43008
#define O_WC2  44544
#define O_G0S  44928
#define O_WPJ  48864
#define O_BPJ  50176
#define O_LG   50224
#define O_TOK  50576
#define SM_FLOATS 50640
#define SM_BYTES (SM_FLOATS * 4)

// ---------------- main persistent pod kernel ----------------
__global__ __launch_bounds__(NTHR, 1)
void k_main(const float* __restrict__ Whh0, const float* __restrict__ bhh0,
            const float* __restrict__ Wih1, const float* __restrict__ Whh1,
            const float* __restrict__ bih1, const float* __restrict__ bhh1,
            const float* __restrict__ Wih2, const float* __restrict__ Whh2,
            const float* __restrict__ bih2, const float* __restrict__ bhh2,
            const float* __restrict__ W_proj, const float* __restrict__ b_proj,
            float* __restrict__ out, float* __restrict__ pred) {
    extern __shared__ __align__(16) float sm[];
    float* wA  = sm + O_WA;    // [256][96]  gates r/z/n of my 32 h0-cols
    float* wB1 = sm + O_WB1;   // [256][48]
    float* wB2 = sm + O_WB2;   // [128][48]
    float* wC1 = sm + O_WC1;   // [128][12]
    float* wC2 = sm + O_WC2;   // [32][12]
    float* G0s = sm + O_G0S;   // [41][96]
    float* wPj = sm + O_WPJ;   // [32][41]
    float* bpj = sm + O_BPJ;
    float* lg  = sm + O_LG;    // [8][44]
    int*  toks = (int*)(sm + O_TOK);  // [64]

    const int tid = threadIdx.x;
    const int slice = blockIdx.x & 7;
    const int pod = blockIdx.x >> 3;
    const int row0 = pod * 64;

    // ---- one-time weight load into smem ----
    for (int i = tid; i < 24576; i += NTHR) {
        int k = i / 96, rem = i - k * 96, g = rem >> 5, j = rem & 31;
        wA[i] = Whh0[(size_t)(g * 256 + slice * 32 + j) * 256 + k];
    }
    for (int i = tid; i < 12288; i += NTHR) {
        int k = i / 48, rem = i - k * 48, g = rem >> 4, j = rem & 15;
        wB1[i] = Wih1[(size_t)(g * 128 + slice * 16 + j) * 256 + k];
    }
    for (int i = tid; i < 6144; i += NTHR) {
        int k = i / 48, rem = i - k * 48, g = rem >> 4, j = rem & 15;
        wB2[i] = Whh1[(size_t)(g * 128 + slice * 16 + j) * 128 + k];
    }
    for (int i = tid; i < 1536; i += NTHR) {
        int k = i / 12, rem = i - k * 12, g = rem >> 2, j = rem & 3;
        wC1[i] = Wih2[(size_t)(g * 32 + slice * 4 + j) * 128 + k];
    }
    for (int i = tid; i < 384; i += NTHR) {
        int k = i / 12, rem = i - k * 12, g = rem >> 2, j = rem & 3;
        wC2[i] = Whh2[(size_t)(g * 32 + slice * 4 + j) * 32 + k];
    }
    for (int i = tid; i < 3936; i += NTHR) {
        int v = i / 96, rem = i - v * 96, g = rem >> 5, j = rem & 31;
        G0s[i] = g_G0[v * 768 + g * 256 + slice * 32 + j];
    }
    for (int i = tid; i < 1312; i += NTHR) {
        int k = i / 41, j = i - k * 41;
        wPj[i] = W_proj[j * 32 + k];
    }
    for (int i = tid; i < Vsz; i += NTHR) bpj[i] = b_proj[i];

    // ---- per-thread roles & biases ----
    const int jA = tid & 31, qA = tid >> 5;           // phase A: col jA, rows qA*8..+7
    const int JA = slice * 32 + jA;
    const int rpA = row0 / 2 + qA * 4;                // u64 rowpair base
    const float bR = bhh0[JA], bZ = bhh0[256 + JA], bN = bhh0[512 + JA];

    const int jB = tid & 15, qB = tid >> 4;           // phase B: col jB, rows qB*4..+3
    const int JB = slice * 16 + jB;
    const int rpB = row0 / 2 + qB * 2;
    const float bBr = bih1[JB] + bhh1[JB];
    const float bBz = bih1[128 + JB] + bhh1[128 + JB];
    const float bBi = bih1[256 + JB], bBh = bhh1[256 + JB];

    const int jC = tid & 3, qC = (tid >> 2) & 31;     // phase C: col jC, rows 2qC,2qC+1
    const int JC = slice * 4 + jC;
    const int rpC = row0 / 2 + qC;
    const float bCr = bih2[JC] + bhh2[JC];
    const float bCz = bih2[32 + JC] + bhh2[32 + JC];
    const float bCi = bih2[64 + JC], bCh = bhh2[64 + JC];

    __syncthreads();

    for (int st = 0; st < Ssz; st++) {
        if (tid < 64) toks[tid] = g_tokT[st * 1024 + row0 + tid];
        __syncthreads();

        const u64* h0p = (const u64*)g_h0r + ((st + 1) & 1) * 131072;
        u64*       h0n = (u64*)g_h0r + (st & 1) * 131072;
        const u64* h1p = (const u64*)g_h1r + ((st + 1) & 1) * 65536;
        u64*       h1n = (u64*)g_h1r + (st & 1) * 65536;
        const u64* h2p = (const u64*)g_h2r + ((st + 1) & 1) * 16384;
        u64*       h2n = (u64*)g_h2r + (st & 1) * 16384;

        // ======== Phase A: layer 0 — my 32 h0-cols x 8 rows ========
        {
            int tk[8];
#pragma unroll
            for (int r = 0; r < 8; r++) tk[r] = toks[qA * 8 + r];
            u64 aR[4], aZ[4], aN[4];
#pragma unroll
            for (int rp = 0; rp < 4; rp++) {
                aR[rp] = pk2(G0s[tk[2 * rp] * 96 + jA] + bR,
                             G0s[tk[2 * rp + 1] * 96 + jA] + bR);
                aZ[rp] = pk2(G0s[tk[2 * rp] * 96 + 32 + jA] + bZ,
                             G0s[tk[2 * rp + 1] * 96 + 32 + jA] + bZ);
                aN[rp] = pk2(bN, bN);
            }
#pragma unroll 4
            for (int k = 0; k < 256; k++) {
                ulonglong2 hX = ldcg2(h0p + k * 512 + rpA);
                ulonglong2 hY = ldcg2(h0p + k * 512 + rpA + 2);
                float wr = wA[k * 96 + jA];
                float wz = wA[k * 96 + 32 + jA];
                float wn = wA[k * 96 + 64 + jA];
                u64 wr2 = pk2(wr, wr), wz2 = pk2(wz, wz), wn2 = pk2(wn, wn);
                aR[0] = fma2(wr2, hX.x, aR[0]); aR[1] = fma2(wr2, hX.y, aR[1]);
                aR[2] = fma2(wr2, hY.x, aR[2]); aR[3] = fma2(wr2, hY.y, aR[3]);
                aZ[0] = fma2(wz2, hX.x, aZ[0]); aZ[1] = fma2(wz2, hX.y, aZ[1]);
                aZ[2] = fma2(wz2, hY.x, aZ[2]); aZ[3] = fma2(wz2, hY.y, aZ[3]);
                aN[0] = fma2(wn2, hX.x, aN[0]); aN[1] = fma2(wn2, hX.y, aN[1]);
                aN[2] = fma2(wn2, hY.x, aN[2]); aN[3] = fma2(wn2, hY.y, aN[3]);
            }
            ulonglong2 hoX = ldcg2(h0p + JA * 512 + rpA);
            ulonglong2 hoY = ldcg2(h0p + JA * 512 + rpA + 2);
            u64 holds[4] = {hoX.x, hoX.y, hoY.x, hoY.y};
#pragma unroll
            for (int rp = 0; rp < 4; rp++) {
                float r0e, r1e, z0e, z1e, n0e, n1e, ho0, ho1;
                up2(aR[rp], r0e, r1e); up2(aZ[rp], z0e, z1e);
                up2(aN[rp], n0e, n1e); up2(holds[rp], ho0, ho1);
                float g0 = G0s[tk[2 * rp] * 96 + 64 + jA];
                float g1 = G0s[tk[2 * rp + 1] * 96 + 64 + jA];
                float rg0 = sigf(r0e), rg1 = sigf(r1e);
                float zg0 = sigf(z0e), zg1 = sigf(z1e);
                float ng0 = tanh_(g0 + rg0 * n0e), ng1 = tanh_(g1 + rg1 * n1e);
                float v0 = (1.0f - zg0) * ng0 + zg0 * ho0;
                float v1 = (1.0f - zg1) * ng1 + zg1 * ho1;
                h0n[JA * 512 + rpA + rp] = pk2(v0, v1);
            }
        }
        pod_barrier(&g_flags[(st * 16 + pod) * 3 + 0]);

        // ======== Phase B: layer 1 — my 16 h1-cols x 4 rows ========
        {
            u64 cR[2], cZ[2], cI[2], cH[2];
            cR[0] = cR[1] = pk2(bBr, bBr);
            cZ[0] = cZ[1] = pk2(bBz, bBz);
            cI[0] = cI[1] = pk2(bBi, bBi);
            cH[0] = cH[1] = pk2(bBh, bBh);
#pragma unroll 4
            for (int k = 0; k < 256; k++) {
                ulonglong2 h = ldcg2((const u64*)h0n + k * 512 + rpB);
                float wr = wB1[k * 48 + jB];
                float wz = wB1[k * 48 + 16 + jB];
                float wn = wB1[k * 48 + 32 + jB];
                u64 wr2 = pk2(wr, wr), wz2 = pk2(wz, wz), wn2 = pk2(wn, wn);
                cR[0] = fma2(wr2, h.x, cR[0]); cR[1] = fma2(wr2, h.y, cR[1]);
                cZ[0] = fma2(wz2, h.x, cZ[0]); cZ[1] = fma2(wz2, h.y, cZ[1]);
                cI[0] = fma2(wn2, h.x, cI[0]); cI[1] = fma2(wn2, h.y, cI[1]);
            }
#pragma unroll 4
            for (int k = 0; k < 128; k++) {
                ulonglong2 h = ldcg2(h1p + k * 512 + rpB);
                float wr = wB2[k * 48 + jB];
                float wz = wB2[k * 48 + 16 + jB];
                float wn = wB2[k * 48 + 32 + jB];
                u64 wr2 = pk2(wr, wr), wz2 = pk2(wz, wz), wn2 = pk2(wn, wn);
                cR[0] = fma2(wr2, h.x, cR[0]); cR[1] = fma2(wr2, h.y, cR[1]);
                cZ[0] = fma2(wz2, h.x, cZ[0]); cZ[1] = fma2(wz2, h.y, cZ[1]);
                cH[0] = fma2(wn2, h.x, cH[0]); cH[1] = fma2(wn2, h.y, cH[1]);
            }
            ulonglong2 hold = ldcg2(h1p + JB * 512 + rpB);
            u64 holds[2] = {hold.x, hold.y};
#pragma unroll
            for (int rp = 0; rp < 2; rp++) {
                float r0e, r1e, z0e, z1e, i0, i1, hh0, hh1, ho0, ho1;
                up2(cR[rp], r0e, r1e); up2(cZ[rp], z0e, z1e);
                up2(cI[rp], i0, i1); up2(cH[rp], hh0, hh1); up2(holds[rp], ho0, ho1);
                float rg0 = sigf(r0e), rg1 = sigf(r1e);
                float zg0 = sigf(z0e), zg1 = sigf(z1e);
                float ng0 = tanh_(i0 + rg0 * hh0), ng1 = tanh_(i1 + rg1 * hh1);
                h1n[JB * 512 + rpB + rp] =
                    pk2((1.0f - zg0) * ng0 + zg0 * ho0, (1.0f - zg1) * ng1 + zg1 * ho1);
            }
        }
        pod_barrier(&g_flags[(st * 16 + pod) * 3 + 1]);

        // ======== Phase C: layer 2 — my 4 h2-cols x 2 rows (tid<128) ========
        if (tid < 128) {
            u64 cR = pk2(bCr, bCr), cZ = pk2(bCz, bCz), cI = pk2(bCi, bCi), cH = pk2(bCh, bCh);
#pragma unroll 4
            for (int k = 0; k < 128; k++) {
                u64 h = ldcg1((const u64*)h1n + k * 512 + rpC);
                float wr = wC1[k * 12 + jC];
                float wz = wC1[k * 12 + 4 + jC];
                float wn = wC1[k * 12 + 8 + jC];
                cR = fma2(pk2(wr, wr), h, cR);
                cZ = fma2(pk2(wz, wz), h, cZ);
                cI = fma2(pk2(wn, wn), h, cI);
            }
#pragma unroll
            for (int k = 0; k < 32; k++) {
                u64 h = ldcg1(h2p + k * 512 + rpC);
                float wr = wC2[k * 12 + jC];
                float wz = wC2[k * 12 + 4 + jC];
                float wn = wC2[k * 12 + 8 + jC];
                cR = fma2(pk2(wr, wr), h, cR);
                cZ = fma2(pk2(wz, wz), h, cZ);
                cH = fma2(pk2(wn, wn), h, cH);
            }
            u64 hold = ldcg1(h2p + JC * 512 + rpC);
            float r0e, r1e, z0e, z1e, i0, i1, hh0, hh1, ho0, ho1;
            up2(cR, r0e, r1e); up2(cZ, z0e, z1e);
            up2(cI, i0, i1); up2(cH, hh0, hh1); up2(hold, ho0, ho1);
            float rg0 = sigf(r0e), rg1 = sigf(r1e);
            float zg0 = sigf(z0e), zg1 = sigf(z1e);
            float ng0 = tanh_(i0 + rg0 * hh0), ng1 = tanh_(i1 + rg1 * hh1);
            h2n[JC * 512 + rpC] =
                pk2((1.0f - zg0) * ng0 + zg0 * ho0, (1.0f - zg1) * ng1 + zg1 * ho1);
        }
        pod_barrier(&g_flags[(st * 16 + pod) * 3 + 2]);

        // ======== Phase D: projection + argmax (my 8 rows) ========
        {
            const float* h2f = (const float*)h2n;
            for (int idx = tid; idx < 8 * Vsz; idx += NTHR) {
                int r = idx / Vsz, j = idx - r * Vsz;
                int gr = row0 + slice * 8 + r;
                float acc = bpj[j];
#pragma unroll
                for (int k = 0; k < 32; k++)
                    acc += wPj[k * 41 + j] * ldcgf(h2f + k * 1024 + gr);
                out[((size_t)gr * Ssz + st) * Vsz + j] = acc;
                lg[r * 44 + j] = acc;
            }
            __syncthreads();
            if (tid < 8 && pred) {
                float best = lg[tid * 44];
                int bi = 0;
#pragma unroll 1
                for (int j = 1; j < Vsz; j++) {
                    float v = lg[tid * 44 + j];
                    if (v > best) { best = v; bi = j; }
                }
                pred[(size_t)(row0 + slice * 8 + tid) * Ssz + st] = (float)bi;
            }
        }
        __syncthreads();
    }
}

// ---------------- launch ----------------
extern "C" void kernel_launch(void* const* d_in, const int* in_sizes, int n_in,
                              void* d_out, int out_size) {
    const float* latent  = (const float*)d_in[0];
    const int*   tokens  = (const int*)d_in[1];
    const float* W_emb   = (const float*)d_in[2];
    const float* b_emb   = (const float*)d_in[3];
    const float* W_init  = (const float*)d_in[4];
    const float* b_init  = (const float*)d_in[5];
    const float* Wih0    = (const float*)d_in[6];
    const float* Whh0    = (const float*)d_in[7];
    const float* bih0    = (const float*)d_in[8];
    const float* bhh0    = (const float*)d_in[9];
    const float* Wih1    = (const float*)d_in[10];
    const float* Whh1    = (const float*)d_in[11];
    const float* bih1    = (const float*)d_in[12];
    const float* bhh1    = (const float*)d_in[13];
    const float* Wih2    = (const float*)d_in[14];
    const float* Whh2    = (const float*)d_in[15];
    const float* bih2    = (const float*)d_in[16];
    const float* bhh2    = (const float*)d_in[17];
    const float* W_proj  = (const float*)d_in[18];
    const float* b_proj  = (const float*)d_in[19];

    float* out = (float*)d_out;
    size_t logits_elems = (size_t)Bsz * Ssz * Vsz;
    float* pred = ((size_t)out_size >= logits_elems + (size_t)Bsz * Ssz)
                      ? out + logits_elems : nullptr;

    cudaFuncSetAttribute(k_main, cudaFuncAttributeMaxDynamicSharedMemorySize, SM_BYTES);

    k_zero<<<(Ssz * 16 * 3 + 255) / 256, 256>>>();
    k_prep<<<177, 256>>>(latent, W_emb, b_emb, W_init, b_init, Wih0, bih0, tokens);
    k_main<<<NCTA, NTHR, SM_BYTES>>>(Whh0, bhh0, Wih1, Whh1, bih1, bhh1,
                                     Wih2, Whh2, bih2, bhh2, W_proj, b_proj, out, pred);
}

// round 10
// speedup vs baseline: 1.6963x; 1.6963x over previous
#include <cuda_runtime.h>
#include <math.h>

#define Bsz 1024
#define Ssz 350
#define Vsz 41
#define BT 8
#define NCTA 128
#define NTHR 256

typedef unsigned long long u64;

// ---------------- persistent device scratch ----------------
__device__ float4 g_A[49152];      // Whh0 e-pair packed: [kc][g][c2][j]
__device__ float4 g_B1rz[16384];   // Wih1 (r,z) pairs: [kc][c2][j]
__device__ float4 g_B1n[8192];     // Wih1 n rows: [kc][j] = 4 k
__device__ float4 g_B2rz[8192];    // Whh1 (r,z)
__device__ float4 g_B2n[4096];
__device__ float4 g_C1rz[2048];    // Wih2
__device__ float4 g_C1n[1024];
__device__ float4 g_C2rz[512];     // Whh2
__device__ float4 g_C2n[256];
__device__ float  g_WprojT[1312];  // [k][j]
__device__ float  g_G0x[41 * 768]; // [v][g][jm][e] pairs (u64-viewable)
__device__ float  g_Hinit[Bsz * 416];

// ---------------- f32x2 helpers ----------------
__device__ __forceinline__ u64 fma2(u64 a, u64 b, u64 c) {
    u64 d; asm("fma.rn.f32x2 %0,%1,%2,%3;" : "=l"(d) : "l"(a), "l"(b), "l"(c)); return d;
}
__device__ __forceinline__ u64 add2(u64 a, u64 b) {
    u64 d; asm("add.rn.f32x2 %0,%1,%2;" : "=l"(d) : "l"(a), "l"(b)); return d;
}
__device__ __forceinline__ u64 pk2(float x, float y) {
    u64 d; asm("mov.b64 %0,{%1,%2};" : "=l"(d) : "f"(x), "f"(y)); return d;
}
__device__ __forceinline__ void up2(u64 a, float& x, float& y) {
    asm("mov.b64 {%0,%1}, %2;" : "=f"(x), "=f"(y) : "l"(a));
}
__device__ __forceinline__ float lo2(u64 a) { float x, y; up2(a, x, y); return x; }

__device__ __forceinline__ float sigf(float x) {
    return __fdividef(1.0f, 1.0f + __expf(-x));
}
__device__ __forceinline__ float tanh_(float x) {
    float ax = fabsf(x);
    float e = __expf(-2.0f * ax);
    float t = __fdividef(1.0f - e, 1.0f + e);
    return copysignf(t, x);
}

// ---------------- fused prep kernel (identical to R2) ----------------
__global__ void k_prep(const float* __restrict__ latent, const float* __restrict__ W_emb,
                       const float* __restrict__ b_emb, const float* __restrict__ W_init,
                       const float* __restrict__ b_init, const float* __restrict__ Wih0,
                       const float* __restrict__ bih0, const float* __restrict__ Whh0,
                       const float* __restrict__ Wih1, const float* __restrict__ Whh1,
                       const float* __restrict__ Wih2, const float* __restrict__ Whh2,
                       const float* __restrict__ W_proj) {
    const int b = blockIdx.x, tid = threadIdx.x;
    if (b < 128) {
        __shared__ float lat[8 * 512];
        const int b0 = b * 8;
        for (int i = tid; i < 8 * 512; i += NTHR) lat[i] = latent[(size_t)b0 * 512 + i];
        __syncthreads();
        for (int c = tid; c < 416; c += NTHR) {
            float acc[8];
            float bi = b_init[c];
#pragma unroll
            for (int r = 0; r < 8; r++) acc[r] = bi;
            const float* w = W_init + (size_t)c * 512;
            for (int k = 0; k < 512; k += 4) {
                float4 wv = *(const float4*)(w + k);
#pragma unroll
                for (int r = 0; r < 8; r++) {
                    acc[r] += wv.x * lat[r * 512 + k];
                    acc[r] += wv.y * lat[r * 512 + k + 1];
                    acc[r] += wv.z * lat[r * 512 + k + 2];
                    acc[r] += wv.w * lat[r * 512 + k + 3];
                }
            }
#pragma unroll
            for (int r = 0; r < 8; r++) g_Hinit[(size_t)(b0 + r) * 416 + c] = acc[r];
        }
    } else if (b < 169) {
        const int v = b - 128;
        __shared__ float emb[512];
        for (int k = tid; k < 512; k += NTHR) emb[k] = W_emb[k * Vsz + v] + b_emb[k];
        __syncthreads();
        for (int j = tid; j < 768; j += NTHR) {
            float acc = bih0[j];
            const float* w = Wih0 + (size_t)j * 512;
            for (int k = 0; k < 512; k += 4) {
                float4 wv = *(const float4*)(w + k);
                acc += wv.x * emb[k] + wv.y * emb[k + 1] + wv.z * emb[k + 2] + wv.w * emb[k + 3];
            }
            int g = j >> 8, rem = j & 255, e = rem >> 7, jm = rem & 127;
            g_G0x[(((size_t)v * 3 + g) * 128 + jm) * 2 + e] = acc;
        }
    } else {
        const int TOTAL = 90184;
        for (int i = (b - 169) * NTHR + tid; i < TOTAL; i += 87 * NTHR) {
            if (i < 49152) {
                int kc = i / 768, rem = i % 768;
                int g = rem / 256, rem2 = rem % 256, c2 = rem2 >> 7, jj = rem2 & 127;
                int k = 4 * kc + 2 * c2, row0 = g * 256 + jj, row1 = row0 + 128;
                g_A[i] = make_float4(Whh0[row0 * 256 + k], Whh0[row1 * 256 + k],
                                     Whh0[row0 * 256 + k + 1], Whh0[row1 * 256 + k + 1]);
            } else if (i < 65536) {
                int t = i - 49152;
                int kc = t / 256, c2 = (t & 255) >> 7, jj = t & 127, k = 4 * kc + 2 * c2;
                g_B1rz[t] = make_float4(Wih1[jj * 256 + k], Wih1[(128 + jj) * 256 + k],
                                        Wih1[jj * 256 + k + 1], Wih1[(128 + jj) * 256 + k + 1]);
            } else if (i < 73728) {
                int t = i - 65536;
                int kc = t >> 7, jj = t & 127;
                g_B1n[t] = *(const float4*)&Wih1[(256 + jj) * 256 + 4 * kc];
            } else if (i < 81920) {
                int t = i - 73728;
                int kc = t / 256, c2 = (t & 255) >> 7, jj = t & 127, k = 4 * kc + 2 * c2;
                g_B2rz[t] = make_float4(Whh1[jj * 128 + k], Whh1[(128 + jj) * 128 + k],
                                        Whh1[jj * 128 + k + 1], Whh1[(128 + jj) * 128 + k + 1]);
            } else if (i < 86016) {
                int t = i - 81920;
                int kc = t >> 7, jj = t & 127;
                g_B2n[t] = *(const float4*)&Whh1[(256 + jj) * 128 + 4 * kc];
            } else if (i < 88064) {
                int t = i - 86016;
                int kc = t / 64, c2 = (t & 63) >> 5, jc = t & 31, k = 4 * kc + 2 * c2;
                g_C1rz[t] = make_float4(Wih2[jc * 128 + k], Wih2[(32 + jc) * 128 + k],
                                        Wih2[jc * 128 + k + 1], Wih2[(32 + jc) * 128 + k + 1]);
            } else if (i < 89088) {
                int t = i - 88064;
                int kc = t >> 5, jc = t & 31;
                g_C1n[t] = *(const float4*)&Wih2[(64 + jc) * 128 + 4 * kc];
            } else if (i < 89600) {
                int t = i - 89088;
                int kc = t / 64, c2 = (t & 63) >> 5, jc = t & 31, k = 4 * kc + 2 * c2;
                g_C2rz[t] = make_float4(Whh2[jc * 32 + k], Whh2[(32 + jc) * 32 + k],
                                        Whh2[jc * 32 + k + 1], Whh2[(32 + jc) * 32 + k + 1]);
            } else if (i < 89856) {
                int t = i - 89600;
                int kc = t >> 5, jc = t & 31;
                g_C2n[t] = *(const float4*)&Whh2[(64 + jc) * 32 + 4 * kc];
            } else {
                int t2 = i - 89856;
#pragma unroll
                for (int c = 0; c < 4; c++) {
                    int e = t2 * 4 + c;
                    if (e < 1312) {
                        int k = e / Vsz, j = e - k * Vsz;
                        g_WprojT[e] = W_proj[j * 32 + k];
                    }
                }
            }
        }
    }
}

// ---------------- main persistent GRU kernel (R2 + weight prefetch, fixed D) ----------------
__global__ __launch_bounds__(NTHR, 1)
void k_main(const int* __restrict__ tokens,
            const float* __restrict__ bhh0,
            const float* __restrict__ bih1, const float* __restrict__ bhh1,
            const float* __restrict__ bih2, const float* __restrict__ bhh2,
            const float* __restrict__ b_proj,
            float* __restrict__ out, float* __restrict__ pred) {
    __shared__ __align__(16) u64 h0d[256 * 8];
    __shared__ __align__(16) u64 h1d[128 * 8];
    __shared__ __align__(16) u64 h2d[32 * 8];
    __shared__ float lg[BT][44];
    __shared__ int toksAll[Ssz * 8];

    const int tid = threadIdx.x;
    const int b0 = blockIdx.x * BT;
    const int jj = tid & 127;
    const int r0 = (tid >> 7) * 4;
    const int jc = tid & 31;
    const int rowC = tid >> 5;

    // tokens preload (SOS at step 0)
    for (int i = tid; i < Ssz * 8; i += NTHR) {
        int stt = i >> 3, row = i & 7;
        toksAll[i] = (stt == 0) ? 1 : tokens[(size_t)(b0 + row) * Ssz + stt];
    }

    // initial state -> dup smem
    for (int idx = tid; idx < BT * 416; idx += NTHR) {
        int row = idx / 416, c = idx - row * 416;
        float v = g_Hinit[(size_t)(b0 + row) * 416 + c];
        if (c < 256)      h0d[c * 8 + row] = pk2(v, v);
        else if (c < 384) h1d[(c - 256) * 8 + row] = pk2(v, v);
        else              h2d[(c - 384) * 8 + row] = pk2(v, v);
    }

    // register-resident packed biases (same as R2)
    const u64 bA_r = pk2(bhh0[jj], bhh0[128 + jj]);
    const u64 bA_z = pk2(bhh0[256 + jj], bhh0[384 + jj]);
    const u64 bA_n = pk2(bhh0[512 + jj], bhh0[640 + jj]);
    const u64 bB_rz = pk2(bih1[jj] + bhh1[jj], bih1[128 + jj] + bhh1[128 + jj]);
    const float b1in = bih1[256 + jj], b1hn = bhh1[256 + jj];
    const u64 bB_in = pk2(b1in, b1in);
    const u64 bB_hn = pk2(b1hn, b1hn);
    const u64 bC_rz = pk2(bih2[jc] + bhh2[jc], bih2[32 + jc] + bhh2[32 + jc]);
    const float b2in = bih2[64 + jc], b2hn = bhh2[64 + jc];
    const u64 bC_in = pk2(b2in, b2in);
    const u64 bC_hn = pk2(b2hn, b2hn);

    const u64* __restrict__ G0p = (const u64*)g_G0x;

    __syncthreads();

    for (int st = 0; st < Ssz; st++) {
        const int* tokrow = toksAll + st * 8;

        // ======== Phase A: layer 0 (e-pair packed), 1-deep weight prefetch ========
        u64 aR[4], aZ[4], aN[4], gIN[4];
#pragma unroll
        for (int r = 0; r < 4; r++) {
            const u64* g = G0p + (size_t)tokrow[r0 + r] * 384;
            aR[r] = add2(g[jj], bA_r);
            aZ[r] = add2(g[128 + jj], bA_z);
            gIN[r] = g[256 + jj];
            aN[r] = bA_n;
        }
        {
            const float4* baseA = g_A + jj;
            ulonglong2 wr0 = *(const ulonglong2*)(baseA);
            ulonglong2 wr1 = *(const ulonglong2*)(baseA + 128);
            ulonglong2 wz0 = *(const ulonglong2*)(baseA + 256);
            ulonglong2 wz1 = *(const ulonglong2*)(baseA + 384);
            ulonglong2 wn0 = *(const ulonglong2*)(baseA + 512);
            ulonglong2 wn1 = *(const ulonglong2*)(baseA + 640);
            for (int kc = 0; kc < 64; kc++) {
                const float4* nb = baseA + (((kc + 1) & 63) * 768);
                ulonglong2 nr0 = *(const ulonglong2*)(nb);
                ulonglong2 nr1 = *(const ulonglong2*)(nb + 128);
                ulonglong2 nz0 = *(const ulonglong2*)(nb + 256);
                ulonglong2 nz1 = *(const ulonglong2*)(nb + 384);
                ulonglong2 nn0 = *(const ulonglong2*)(nb + 512);
                ulonglong2 nn1 = *(const ulonglong2*)(nb + 640);
                u64 wR[4] = {wr0.x, wr0.y, wr1.x, wr1.y};
                u64 wZ[4] = {wz0.x, wz0.y, wz1.x, wz1.y};
                u64 wN[4] = {wn0.x, wn0.y, wn1.x, wn1.y};
                u64 hv[4][4];
#pragma unroll
                for (int c = 0; c < 4; c++) {
                    ulonglong2 ha = *(const ulonglong2*)&h0d[(4 * kc + c) * 8 + r0];
                    ulonglong2 hb = *(const ulonglong2*)&h0d[(4 * kc + c) * 8 + r0 + 2];
                    hv[c][0] = ha.x; hv[c][1] = ha.y; hv[c][2] = hb.x; hv[c][3] = hb.y;
                }
#pragma unroll
                for (int c = 0; c < 4; c++)
#pragma unroll
                    for (int r = 0; r < 4; r++) {
                        aR[r] = fma2(wR[c], hv[c][r], aR[r]);
                        aZ[r] = fma2(wZ[c], hv[c][r], aZ[r]);
                        aN[r] = fma2(wN[c], hv[c][r], aN[r]);
                    }
                wr0 = nr0; wr1 = nr1; wz0 = nz0; wz1 = nz1; wn0 = nn0; wn1 = nn1;
            }
        }
        __syncthreads();
#pragma unroll
        for (int r = 0; r < 4; r++) {
            float r0e, r1e, z0e, z1e, n0e, n1e, i0e, i1e;
            up2(aR[r], r0e, r1e); up2(aZ[r], z0e, z1e);
            up2(aN[r], n0e, n1e); up2(gIN[r], i0e, i1e);
            float hold0 = lo2(h0d[jj * 8 + r0 + r]);
            float hold1 = lo2(h0d[(128 + jj) * 8 + r0 + r]);
            float rg0 = sigf(r0e), rg1 = sigf(r1e);
            float zg0 = sigf(z0e), zg1 = sigf(z1e);
            float ng0 = tanh_(i0e + rg0 * n0e), ng1 = tanh_(i1e + rg1 * n1e);
            float v0 = (1.0f - zg0) * ng0 + zg0 * hold0;
            float v1 = (1.0f - zg1) * ng1 + zg1 * hold1;
            h0d[jj * 8 + r0 + r] = pk2(v0, v0);
            h0d[(128 + jj) * 8 + r0 + r] = pk2(v1, v1);
        }
        __syncthreads();

        // ======== Phase B: layer 1 (gate-pair packed), prefetched ========
        u64 rz[4], iN[4], hN[4];
#pragma unroll
        for (int r = 0; r < 4; r++) { rz[r] = bB_rz; iN[r] = bB_in; hN[r] = bB_hn; }
        {
            const float4* base1 = g_B1rz + jj;
            const float4* basen = g_B1n + jj;
            ulonglong2 w01 = *(const ulonglong2*)(base1);
            ulonglong2 w23 = *(const ulonglong2*)(base1 + 128);
            float4 wn4 = *basen;
            for (int kc = 0; kc < 64; kc++) {
                int nkc = (kc + 1) & 63;
                ulonglong2 n01 = *(const ulonglong2*)(base1 + nkc * 256);
                ulonglong2 n23 = *(const ulonglong2*)(base1 + nkc * 256 + 128);
                float4 nn4 = *(basen + nkc * 128);
                u64 wrz[4] = {w01.x, w01.y, w23.x, w23.y};
                u64 wnd[4] = {pk2(wn4.x, wn4.x), pk2(wn4.y, wn4.y),
                              pk2(wn4.z, wn4.z), pk2(wn4.w, wn4.w)};
                u64 hv[4][4];
#pragma unroll
                for (int c = 0; c < 4; c++) {
                    ulonglong2 ha = *(const ulonglong2*)&h0d[(4 * kc + c) * 8 + r0];
                    ulonglong2 hb = *(const ulonglong2*)&h0d[(4 * kc + c) * 8 + r0 + 2];
                    hv[c][0] = ha.x; hv[c][1] = ha.y; hv[c][2] = hb.x; hv[c][3] = hb.y;
                }
#pragma unroll
                for (int c = 0; c < 4; c++)
#pragma unroll
                    for (int r = 0; r < 4; r++) {
                        rz[r] = fma2(wrz[c], hv[c][r], rz[r]);
                        iN[r] = fma2(wnd[c], hv[c][r], iN[r]);
                    }
                w01 = n01; w23 = n23; wn4 = nn4;
            }
        }
        {
            const float4* base2 = g_B2rz + jj;
            const float4* basen = g_B2n + jj;
            ulonglong2 w01 = *(const ulonglong2*)(base2);
            ulonglong2 w23 = *(const ulonglong2*)(base2 + 128);
            float4 wn4 = *basen;
            for (int kc = 0; kc < 32; kc++) {
                int nkc = (kc + 1) & 31;
                ulonglong2 n01 = *(const ulonglong2*)(base2 + nkc * 256);
                ulonglong2 n23 = *(const ulonglong2*)(base2 + nkc * 256 + 128);
                float4 nn4 = *(basen + nkc * 128);
                u64 wrz[4] = {w01.x, w01.y, w23.x, w23.y};
                u64 wnd[4] = {pk2(wn4.x, wn4.x), pk2(wn4.y, wn4.y),
                              pk2(wn4.z, wn4.z), pk2(wn4.w, wn4.w)};
                u64 hv[4][4];
#pragma unroll
                for (int c = 0; c < 4; c++) {
                    ulonglong2 ha = *(const ulonglong2*)&h1d[(4 * kc + c) * 8 + r0];
                    ulonglong2 hb = *(const ulonglong2*)&h1d[(4 * kc + c) * 8 + r0 + 2];
                    hv[c][0] = ha.x; hv[c][1] = ha.y; hv[c][2] = hb.x; hv[c][3] = hb.y;
                }
#pragma unroll
                for (int c = 0; c < 4; c++)
#pragma unroll
                    for (int r = 0; r < 4; r++) {
                        rz[r] = fma2(wrz[c], hv[c][r], rz[r]);
                        hN[r] = fma2(wnd[c], hv[c][r], hN[r]);
                    }
                w01 = n01; w23 = n23; wn4 = nn4;
            }
        }
        __syncthreads();
#pragma unroll
        for (int r = 0; r < 4; r++) {
            float ar, az;
            up2(rz[r], ar, az);
            float hold = lo2(h1d[jj * 8 + r0 + r]);
            float rg = sigf(ar), zg = sigf(az);
            float ng = tanh_(lo2(iN[r]) + rg * lo2(hN[r]));
            float v = (1.0f - zg) * ng + zg * hold;
            h1d[jj * 8 + r0 + r] = pk2(v, v);
        }
        __syncthreads();

        // ======== Phase C: layer 2 (prefetched) ========
        u64 rz2 = bC_rz, iN2 = bC_in, hN2 = bC_hn;
        {
            const float4* base1 = g_C1rz + jc;
            const float4* basen = g_C1n + jc;
            ulonglong2 w01 = *(const ulonglong2*)(base1);
            ulonglong2 w23 = *(const ulonglong2*)(base1 + 32);
            float4 wn4 = *basen;
            for (int kc = 0; kc < 32; kc++) {
                int nkc = (kc + 1) & 31;
                ulonglong2 n01 = *(const ulonglong2*)(base1 + nkc * 64);
                ulonglong2 n23 = *(const ulonglong2*)(base1 + nkc * 64 + 32);
                float4 nn4 = *(basen + nkc * 32);
                u64 wrz[4] = {w01.x, w01.y, w23.x, w23.y};
                u64 wnd[4] = {pk2(wn4.x, wn4.x), pk2(wn4.y, wn4.y),
                              pk2(wn4.z, wn4.z), pk2(wn4.w, wn4.w)};
#pragma unroll
                for (int c = 0; c < 4; c++) {
                    u64 h = h1d[(4 * kc + c) * 8 + rowC];
                    rz2 = fma2(wrz[c], h, rz2);
                    iN2 = fma2(wnd[c], h, iN2);
                }
                w01 = n01; w23 = n23; wn4 = nn4;
            }
        }
        for (int kc = 0; kc < 8; kc++) {
            const float4* brz = g_C2rz + kc * 64;
            ulonglong2 w01 = *(const ulonglong2*)(brz + jc);
            ulonglong2 w23 = *(const ulonglong2*)(brz + 32 + jc);
            float4 wn4 = g_C2n[kc * 32 + jc];
            u64 wrz[4] = {w01.x, w01.y, w23.x, w23.y};
            u64 wnd[4] = {pk2(wn4.x, wn4.x), pk2(wn4.y, wn4.y),
                          pk2(wn4.z, wn4.z), pk2(wn4.w, wn4.w)};
#pragma unroll
            for (int c = 0; c < 4; c++) {
                u64 h = h2d[(4 * kc + c) * 8 + rowC];
                rz2 = fma2(wrz[c], h, rz2);
                hN2 = fma2(wnd[c], h, hN2);
            }
        }
        __syncthreads();
        {
            float cr, cz;
            up2(rz2, cr, cz);
            float hold = lo2(h2d[jc * 8 + rowC]);
            float rg = sigf(cr), zg = sigf(cz);
            float ng = tanh_(lo2(iN2) + rg * lo2(hN2));
            float v = (1.0f - zg) * ng + zg * hold;
            h2d[jc * 8 + rowC] = pk2(v, v);
        }
        __syncthreads();

        // ======== Phase D: projection + argmax (grid-stride, covers all 328) ========
        for (int idx = tid; idx < BT * Vsz; idx += NTHR) {
            int row = idx / Vsz, j = idx - row * Vsz;
            float acc = b_proj[j];
#pragma unroll
            for (int k = 0; k < 32; k++)
                acc += g_WprojT[k * Vsz + j] * lo2(h2d[k * 8 + row]);
            out[((size_t)(b0 + row) * Ssz + st) * Vsz + j] = acc;
            lg[row][j] = acc;
        }
        __syncthreads();
        if (tid < BT && pred) {
            float best = lg[tid][0];
            int bi = 0;
#pragma unroll 1
            for (int j = 1; j < Vsz; j++) {
                float v = lg[tid][j];
                if (v > best) { best = v; bi = j; }
            }
            pred[(size_t)(b0 + tid) * Ssz + st] = (float)bi;
        }
        __syncthreads();
    }
}

// ---------------- launch ----------------
extern "C" void kernel_launch(void* const* d_in, const int* in_sizes, int n_in,
                              void* d_out, int out_size) {
    const float* latent  = (const float*)d_in[0];
    const int*   tokens  = (const int*)d_in[1];
    const float* W_emb   = (const float*)d_in[2];
    const float* b_emb   = (const float*)d_in[3];
    const float* W_init  = (const float*)d_in[4];
    const float* b_init  = (const float*)d_in[5];
    const float* Wih0    = (const float*)d_in[6];
    const float* Whh0    = (const float*)d_in[7];
    const float* bih0    = (const float*)d_in[8];
    const float* bhh0    = (const float*)d_in[9];
    const float* Wih1    = (const float*)d_in[10];
    const float* Whh1    = (const float*)d_in[11];
    const float* bih1    = (const float*)d_in[12];
    const float* bhh1    = (const float*)d_in[13];
    const float* Wih2    = (const float*)d_in[14];
    const float* Whh2    = (const float*)d_in[15];
    const float* bih2    = (const float*)d_in[16];
    const float* bhh2    = (const float*)d_in[17];
    const float* W_proj  = (const float*)d_in[18];
    const float* b_proj  = (const float*)d_in[19];

    float* out = (float*)d_out;
    size_t logits_elems = (size_t)Bsz * Ssz * Vsz;
    float* pred = ((size_t)out_size >= logits_elems + (size_t)Bsz * Ssz)
                      ? out + logits_elems : nullptr;

    k_prep<<<256, NTHR>>>(latent, W_emb, b_emb, W_init, b_init, Wih0, bih0, Whh0,
                          Wih1, Whh1, Wih2, Whh2, W_proj);
    k_main<<<NCTA, NTHR>>>(tokens, bhh0, bih1, bhh1, bih2, bhh2, b_proj, out, pred);
}